// round 1
// baseline (speedup 1.0000x reference)
#include <cuda_runtime.h>

#define H    16
#define NBOX 128
#define DIN  256
#define DKD  128
#define DG   64

// Scratch (device globals — no allocations allowed)
__device__ float g_glog[H * NBOX * NBOX];      // log(clip(relu(gate))) per head: 1 MB
__device__ float g_qkv[3 * H * NBOX * DKD];    // k,q,v projections: 3 MB
__device__ float g_partial[H * 4 * DKD];       // per-mtile partial colsums
__device__ float g_colsum[H * DKD];            // final column sums

// ---------------------------------------------------------------------------
// K_gate: glog[h, m, n] = log(max(pos[m,n,:]·WG[h] + bg[h], 1e-6))
// One pass over pos (4 MB) computing all 16 heads at once.
// grid: 256 blocks, 64 (m,n)-pairs each; 256 threads.
// ---------------------------------------------------------------------------
__global__ void k_gate(const float* __restrict__ pos,
                       const float* __restrict__ WG,
                       const float* __restrict__ bg) {
    __shared__ __align__(16) float pos_s[64][65];   // padded: conflict-free
    __shared__ __align__(16) float wg_s[H * DG];    // 16x64

    int tid = threadIdx.x;
    int p0  = blockIdx.x * 64;   // global pair base (pair = m*128 + n)

    // Load WG: 1024 floats = 256 float4, one per thread
    {
        float4 w4 = ((const float4*)WG)[tid];
        ((float4*)wg_s)[tid] = w4;
    }
    // Load pos tile: 64 pairs x 64 g = 1024 float4
#pragma unroll
    for (int it = 0; it < 4; ++it) {
        int fidx = tid + 256 * it;        // 0..1023
        int pl   = fidx >> 4;             // 0..63
        int g4   = fidx & 15;
        float4 v = ((const float4*)pos)[(long)(p0 + pl) * 16 + g4];
        pos_s[pl][g4 * 4 + 0] = v.x;
        pos_s[pl][g4 * 4 + 1] = v.y;
        pos_s[pl][g4 * 4 + 2] = v.z;
        pos_s[pl][g4 * 4 + 3] = v.w;
    }
    __syncthreads();

    int row = tid & 63;          // local pair
    int hg  = tid >> 6;          // 0..3 -> heads {hg, hg+4, hg+8, hg+12}
    float acc[4] = {0.f, 0.f, 0.f, 0.f};
#pragma unroll
    for (int g = 0; g < DG; ++g) {
        float pv = pos_s[row][g];
#pragma unroll
        for (int j = 0; j < 4; ++j)
            acc[j] = fmaf(pv, wg_s[(hg + 4 * j) * DG + g], acc[j]);
    }
#pragma unroll
    for (int j = 0; j < 4; ++j) {
        int h = hg + 4 * j;
        float x = acc[j] + bg[h];
        g_glog[h * (NBOX * NBOX) + p0 + row] = __logf(fmaxf(x, 1e-6f));
    }
}

// ---------------------------------------------------------------------------
// K_proj: for (h, p) compute  out = f_a(128x256) @ W[h](256x128) + b[h]
// grid: (4 mtiles, 3 projections, 16 heads), 256 threads.
// Tile 32 rows x 128 cols; thread = 4 rows x 4 interleaved cols.
// ---------------------------------------------------------------------------
__global__ void k_proj(const float* __restrict__ f_a,
                       const float* __restrict__ WK, const float* __restrict__ bk,
                       const float* __restrict__ WQ, const float* __restrict__ bq,
                       const float* __restrict__ WV, const float* __restrict__ bv) {
    __shared__ __align__(16) float As[32][36];
    __shared__ __align__(16) float Bs[32][132];

    int tid = threadIdx.x;
    int mt = blockIdx.x, p = blockIdx.y, h = blockIdx.z;
    const float* W  = (p == 0) ? WK : ((p == 1) ? WQ : WV);
    const float* bb = (p == 0) ? bk : ((p == 1) ? bq : bv);

    int m0 = mt * 32;
    int w  = tid >> 5;     // warp 0..7 -> rows 4w..4w+3
    int tc = tid & 31;     // cols tc + 32j

    float acc[4][4] = {};

    for (int kk = 0; kk < DIN; kk += 32) {
        // As fill: 32x32 chunk of f_a (coalesced float4)
        {
            int r = tid >> 3, c4 = tid & 7;
            float4 v = *(const float4*)&f_a[(m0 + r) * DIN + kk + 4 * c4];
            *(float4*)&As[r][4 * c4] = v;
        }
        // Bs fill: 32x128 chunk of W[h] (coalesced float4)
#pragma unroll
        for (int it = 0; it < 4; ++it) {
            int fidx = tid + 256 * it;
            int d = fidx >> 5, k4 = fidx & 31;
            float4 v = *(const float4*)&W[((long)h * DIN + kk + d) * DKD + 4 * k4];
            *(float4*)&Bs[d][4 * k4] = v;
        }
        __syncthreads();

#pragma unroll
        for (int d = 0; d < 32; ++d) {
            float a0 = As[4 * w + 0][d];
            float a1 = As[4 * w + 1][d];
            float a2 = As[4 * w + 2][d];
            float a3 = As[4 * w + 3][d];
#pragma unroll
            for (int j = 0; j < 4; ++j) {
                float b = Bs[d][tc + 32 * j];
                acc[0][j] = fmaf(a0, b, acc[0][j]);
                acc[1][j] = fmaf(a1, b, acc[1][j]);
                acc[2][j] = fmaf(a2, b, acc[2][j]);
                acc[3][j] = fmaf(a3, b, acc[3][j]);
            }
        }
        __syncthreads();
    }

    float* outp = g_qkv + ((long)(p * H + h) * NBOX) * DKD;
#pragma unroll
    for (int i = 0; i < 4; ++i) {
#pragma unroll
        for (int j = 0; j < 4; ++j) {
            int col = tc + 32 * j;
            outp[(m0 + 4 * w + i) * DKD + col] = acc[i][j] + bb[h * DKD + col];
        }
    }
}

// ---------------------------------------------------------------------------
// K_attn: score tile = k[m,:]·q[n,:] for 32 rows x 128 cols, add glog,
// warp-level row softmax, accumulate partial column sums (deterministic).
// grid: (4 mtiles, 16 heads), 256 threads.
// ---------------------------------------------------------------------------
__global__ void k_attn() {
    __shared__ __align__(16) float As[32][36];
    __shared__ float Bs[32][132];
    __shared__ float psum[8][128];

    int tid = threadIdx.x;
    int mt = blockIdx.x, h = blockIdx.y;
    int m0 = mt * 32;
    int w  = tid >> 5;
    int tc = tid & 31;

    const float* kmat = g_qkv + (long)(0 * H + h) * NBOX * DKD;
    const float* qmat = g_qkv + (long)(1 * H + h) * NBOX * DKD;

    float acc[4][4] = {};

    for (int kk = 0; kk < DKD; kk += 32) {
        // As: k rows m0..m0+31, cols kk..kk+31
        {
            int r = tid >> 3, c4 = tid & 7;
            float4 v = *(const float4*)&kmat[(m0 + r) * DKD + kk + 4 * c4];
            *(float4*)&As[r][4 * c4] = v;
        }
        // Bs: transpose of q[0..127][kk..kk+31] -> Bs[d][n]
#pragma unroll
        for (int it = 0; it < 4; ++it) {
            int fidx = tid + 256 * it;
            int n = fidx >> 3, c4 = fidx & 7;
            float4 v = *(const float4*)&qmat[n * DKD + kk + 4 * c4];
            Bs[4 * c4 + 0][n] = v.x;
            Bs[4 * c4 + 1][n] = v.y;
            Bs[4 * c4 + 2][n] = v.z;
            Bs[4 * c4 + 3][n] = v.w;
        }
        __syncthreads();

#pragma unroll
        for (int d = 0; d < 32; ++d) {
            float a0 = As[4 * w + 0][d];
            float a1 = As[4 * w + 1][d];
            float a2 = As[4 * w + 2][d];
            float a3 = As[4 * w + 3][d];
#pragma unroll
            for (int j = 0; j < 4; ++j) {
                float b = Bs[d][tc + 32 * j];
                acc[0][j] = fmaf(a0, b, acc[0][j]);
                acc[1][j] = fmaf(a1, b, acc[1][j]);
                acc[2][j] = fmaf(a2, b, acc[2][j]);
                acc[3][j] = fmaf(a3, b, acc[3][j]);
            }
        }
        __syncthreads();
    }

    // logits + softmax per row (each warp fully owns rows 4w..4w+3)
    const float scale = 0.08838834764831843f;  // 1/sqrt(128)
    float csum[4] = {0.f, 0.f, 0.f, 0.f};
#pragma unroll
    for (int i = 0; i < 4; ++i) {
        int m = m0 + 4 * w + i;
        float l[4];
#pragma unroll
        for (int j = 0; j < 4; ++j)
            l[j] = acc[i][j] * scale + g_glog[((long)h * NBOX + m) * NBOX + tc + 32 * j];

        float mx = fmaxf(fmaxf(l[0], l[1]), fmaxf(l[2], l[3]));
#pragma unroll
        for (int off = 16; off; off >>= 1)
            mx = fmaxf(mx, __shfl_xor_sync(0xffffffffu, mx, off));

        float e[4], s = 0.f;
#pragma unroll
        for (int j = 0; j < 4; ++j) { e[j] = __expf(l[j] - mx); s += e[j]; }
#pragma unroll
        for (int off = 16; off; off >>= 1)
            s += __shfl_xor_sync(0xffffffffu, s, off);

        float rinv = 1.0f / s;
#pragma unroll
        for (int j = 0; j < 4; ++j) csum[j] += e[j] * rinv;
    }

#pragma unroll
    for (int j = 0; j < 4; ++j) psum[w][tc + 32 * j] = csum[j];
    __syncthreads();

    if (tid < 128) {
        float s = 0.f;
#pragma unroll
        for (int ww = 0; ww < 8; ++ww) s += psum[ww][tid];
        g_partial[(h * 4 + mt) * DKD + tid] = s;
    }
}

// ---------------------------------------------------------------------------
// K_red: colsum[h][n] = sum over 4 mtile partials (deterministic)
// ---------------------------------------------------------------------------
__global__ void k_red() {
    int t = blockIdx.x * 256 + threadIdx.x;  // 0..2047
    if (t < H * DKD) {
        int h = t >> 7, n = t & 127;
        float s = 0.f;
#pragma unroll
        for (int mt = 0; mt < 4; ++mt) s += g_partial[((h << 2) + mt) * DKD + n];
        g_colsum[t] = s;
    }
}

// ---------------------------------------------------------------------------
// K_out: out[i, c, d] = v[h,i,k]*colsum[h,k] + f_a[i,d]   (c = h*128+k)
// 16,777,216 float4 stores; HBM-write-bound.
// ---------------------------------------------------------------------------
__global__ void k_out(const float* __restrict__ f_a, float4* __restrict__ out) {
    int idx = blockIdx.x * 256 + threadIdx.x;   // 0..2^24-1
    int d4 = idx & 63;
    int c  = (idx >> 6) & 2047;
    int i  = idx >> 17;
    int h  = c >> 7;
    int k  = c & 127;

    float s = g_qkv[((long)(2 * H + h) * NBOX + i) * DKD + k] * g_colsum[c];
    float4 f = ((const float4*)f_a)[i * 64 + d4];
    out[idx] = make_float4(s + f.x, s + f.y, s + f.z, s + f.w);
}

// ---------------------------------------------------------------------------
extern "C" void kernel_launch(void* const* d_in, const int* in_sizes, int n_in,
                              void* d_out, int out_size) {
    const float* f_a = (const float*)d_in[0];
    const float* pos = (const float*)d_in[1];
    const float* WG  = (const float*)d_in[2];
    const float* bg  = (const float*)d_in[3];
    const float* WK  = (const float*)d_in[4];
    const float* bk  = (const float*)d_in[5];
    const float* WQ  = (const float*)d_in[6];
    const float* bq  = (const float*)d_in[7];
    const float* WV  = (const float*)d_in[8];
    const float* bv  = (const float*)d_in[9];

    k_gate<<<256, 256>>>(pos, WG, bg);
    k_proj<<<dim3(4, 3, 16), 256>>>(f_a, WK, bk, WQ, bq, WV, bv);
    k_attn<<<dim3(4, 16), 256>>>();
    k_red<<<8, 256>>>();
    k_out<<<65536, 256>>>(f_a, (float4*)d_out);
}

// round 2
// speedup vs baseline: 1.2396x; 1.2396x over previous
#include <cuda_runtime.h>

#define H    16
#define NBOX 128
#define DIN  256
#define DKD  128
#define DG   64

typedef unsigned long long ull;

// Scratch (device globals — no allocations allowed)
__device__ float g_glog[H * NBOX * NBOX];      // log(clip(relu(gate))): 1 MB
__device__ float g_qkv[3 * H * NBOX * DKD];    // k,q,v projections: 3 MB
__device__ float g_partial[H * 4 * DKD];       // per-mtile partial colsums

// ---- packed f32x2 helpers (sm_10x FFMA2) ----------------------------------
__device__ __forceinline__ void fma2(ull& acc, ull a, ull b) {
    asm("fma.rn.f32x2 %0, %1, %2, %0;" : "+l"(acc) : "l"(a), "l"(b));
}
__device__ __forceinline__ ull dup2(float a) {
    ull r; asm("mov.b64 %0, {%1, %1};" : "=l"(r) : "f"(a)); return r;
}
__device__ __forceinline__ float2 unpack2(ull v) {
    float2 r; asm("mov.b64 {%0, %1}, %2;" : "=f"(r.x), "=f"(r.y) : "l"(v)); return r;
}

// ---------------------------------------------------------------------------
// k_front: fused gate + projections.
//   blocks [0,192):   proj tile (mt in 0..3, p in 0..2, h in 0..15)
//                     C(32x128) = f_a(32x256) @ W[h](256x128) + b
//   blocks [192,448): gate: glog[h,m,n] = log(max(pos[m,n,:]·WG[h]+bg[h],1e-6))
// 256 threads.
// ---------------------------------------------------------------------------
__global__ void k_front(const float* __restrict__ f_a,
                        const float* __restrict__ pos,
                        const float* __restrict__ WG, const float* __restrict__ bg,
                        const float* __restrict__ WK, const float* __restrict__ bk,
                        const float* __restrict__ WQ, const float* __restrict__ bq,
                        const float* __restrict__ WV, const float* __restrict__ bv) {
    __shared__ __align__(16) char smem_raw[25344];  // max(proj 25344, gate 20736)
    int tid = threadIdx.x;

    if (blockIdx.x < 192) {
        // ---------------- proj path ----------------
        ull (*As2)[33] = (ull(*)[33])smem_raw;                   // 32x33 ull (dup'd A)
        ull (*Bs2)[66] = (ull(*)[66])(smem_raw + 32 * 33 * 8);   // 32x66 ull (=128 cols)

        int bid = blockIdx.x;
        int mt = bid & 3;
        int p  = (bid >> 2) % 3;
        int h  = bid / 12;
        const float* W  = (p == 0) ? WK : ((p == 1) ? WQ : WV);
        const float* bb = (p == 0) ? bk : ((p == 1) ? bq : bv);

        int m0 = mt * 32;
        int rg = tid >> 5;     // warp -> rows 4rg..4rg+3
        int cg = tid & 31;     // cols 4cg..4cg+3 (two f32x2 pairs)

        ull acc[4][2] = {};

        for (int kk = 0; kk < DIN; kk += 32) {
            // A fill: 32x32 chunk, duplicated into f32x2 lanes
            {
                int r = tid >> 3, c4 = tid & 7;
                float4 v = *(const float4*)&f_a[(m0 + r) * DIN + kk + 4 * c4];
                As2[r][4 * c4 + 0] = dup2(v.x);
                As2[r][4 * c4 + 1] = dup2(v.y);
                As2[r][4 * c4 + 2] = dup2(v.z);
                As2[r][4 * c4 + 3] = dup2(v.w);
            }
            // B fill: 32x128 chunk of W[h]
#pragma unroll
            for (int it = 0; it < 4; ++it) {
                int fidx = tid + 256 * it;
                int d = fidx >> 5, k4 = fidx & 31;
                float4 v = *(const float4*)&W[((long)h * DIN + kk + d) * DKD + 4 * k4];
                *(float4*)&Bs2[d][2 * k4] = v;
            }
            __syncthreads();

#pragma unroll
            for (int d = 0; d < 32; ++d) {
                ulonglong2 b = *(ulonglong2*)&Bs2[d][2 * cg];
#pragma unroll
                for (int i = 0; i < 4; ++i) {
                    ull a = As2[4 * rg + i][d];
                    fma2(acc[i][0], a, b.x);
                    fma2(acc[i][1], a, b.y);
                }
            }
            __syncthreads();
        }

        float* outp = g_qkv + (long)(p * H + h) * NBOX * DKD;
        float4 b4 = *(const float4*)&bb[h * DKD + 4 * cg];
#pragma unroll
        for (int i = 0; i < 4; ++i) {
            float2 lo = unpack2(acc[i][0]);
            float2 hi = unpack2(acc[i][1]);
            *(float4*)&outp[(m0 + 4 * rg + i) * DKD + 4 * cg] =
                make_float4(lo.x + b4.x, lo.y + b4.y, hi.x + b4.z, hi.y + b4.w);
        }
    } else {
        // ---------------- gate path ----------------
        float (*pos_s)[65] = (float(*)[65])smem_raw;             // 64x65
        float* wg_s = (float*)(smem_raw + 64 * 65 * 4);          // 16x64

        int p0 = (blockIdx.x - 192) * 64;   // pair base (pair = m*128+n)

        ((float4*)wg_s)[tid] = ((const float4*)WG)[tid];
#pragma unroll
        for (int it = 0; it < 4; ++it) {
            int fidx = tid + 256 * it;
            int pl = fidx >> 4, g4 = fidx & 15;
            float4 v = ((const float4*)pos)[(long)(p0 + pl) * 16 + g4];
            pos_s[pl][4 * g4 + 0] = v.x;
            pos_s[pl][4 * g4 + 1] = v.y;
            pos_s[pl][4 * g4 + 2] = v.z;
            pos_s[pl][4 * g4 + 3] = v.w;
        }
        __syncthreads();

        int row = tid & 63;
        int hg  = tid >> 6;       // heads {hg, hg+4, hg+8, hg+12}
        float acc[4] = {0.f, 0.f, 0.f, 0.f};
#pragma unroll
        for (int g = 0; g < DG; ++g) {
            float pv = pos_s[row][g];
#pragma unroll
            for (int j = 0; j < 4; ++j)
                acc[j] = fmaf(pv, wg_s[(hg + 4 * j) * DG + g], acc[j]);
        }
#pragma unroll
        for (int j = 0; j < 4; ++j) {
            int h = hg + 4 * j;
            float x = acc[j] + bg[h];
            g_glog[h * (NBOX * NBOX) + p0 + row] = __logf(fmaxf(x, 1e-6f));
        }
    }
}

// ---------------------------------------------------------------------------
// k_attn: 32x128 score tile (f32x2 FMA), + glog, row softmax, partial colsums.
// grid (4, 16), 256 threads. Thread = rows 4rg..4rg+3 x cols 4cg..4cg+3.
// ---------------------------------------------------------------------------
__global__ void k_attn() {
    __shared__ __align__(16) ull As2[32][33];
    __shared__ __align__(16) float Bs[32][132];
    __shared__ float psum[8][128];

    int tid = threadIdx.x;
    int mt = blockIdx.x, h = blockIdx.y;
    int m0 = mt * 32;
    int rg = tid >> 5;
    int cg = tid & 31;

    const float* kmat = g_qkv + (long)(0 * H + h) * NBOX * DKD;
    const float* qmat = g_qkv + (long)(1 * H + h) * NBOX * DKD;

    ull acc[4][2] = {};

    for (int kk = 0; kk < DKD; kk += 32) {
        // A: k rows (duplicated)
        {
            int r = tid >> 3, c4 = tid & 7;
            float4 v = *(const float4*)&kmat[(m0 + r) * DKD + kk + 4 * c4];
            As2[r][4 * c4 + 0] = dup2(v.x);
            As2[r][4 * c4 + 1] = dup2(v.y);
            As2[r][4 * c4 + 2] = dup2(v.z);
            As2[r][4 * c4 + 3] = dup2(v.w);
        }
        // B: transpose q -> Bs[d][n]
#pragma unroll
        for (int it = 0; it < 4; ++it) {
            int fidx = tid + 256 * it;
            int n = fidx >> 3, c4 = fidx & 7;
            float4 v = *(const float4*)&qmat[n * DKD + kk + 4 * c4];
            Bs[4 * c4 + 0][n] = v.x;
            Bs[4 * c4 + 1][n] = v.y;
            Bs[4 * c4 + 2][n] = v.z;
            Bs[4 * c4 + 3][n] = v.w;
        }
        __syncthreads();

#pragma unroll
        for (int d = 0; d < 32; ++d) {
            ulonglong2 b = *(ulonglong2*)&Bs[d][4 * cg];
#pragma unroll
            for (int i = 0; i < 4; ++i) {
                ull a = As2[4 * rg + i][d];
                fma2(acc[i][0], a, b.x);
                fma2(acc[i][1], a, b.y);
            }
        }
        __syncthreads();
    }

    const float scale = 0.08838834764831843f;  // 1/sqrt(128)
    float csum[4] = {0.f, 0.f, 0.f, 0.f};
#pragma unroll
    for (int i = 0; i < 4; ++i) {
        int m = m0 + 4 * rg + i;
        float4 gl = *(const float4*)&g_glog[((long)h * NBOX + m) * NBOX + 4 * cg];
        float2 s0 = unpack2(acc[i][0]);
        float2 s1 = unpack2(acc[i][1]);
        float l[4];
        l[0] = s0.x * scale + gl.x;
        l[1] = s0.y * scale + gl.y;
        l[2] = s1.x * scale + gl.z;
        l[3] = s1.y * scale + gl.w;

        float mx = fmaxf(fmaxf(l[0], l[1]), fmaxf(l[2], l[3]));
#pragma unroll
        for (int off = 16; off; off >>= 1)
            mx = fmaxf(mx, __shfl_xor_sync(0xffffffffu, mx, off));

        float e[4], s = 0.f;
#pragma unroll
        for (int j = 0; j < 4; ++j) { e[j] = __expf(l[j] - mx); s += e[j]; }
#pragma unroll
        for (int off = 16; off; off >>= 1)
            s += __shfl_xor_sync(0xffffffffu, s, off);

        float rinv = 1.0f / s;
#pragma unroll
        for (int j = 0; j < 4; ++j) csum[j] += e[j] * rinv;
    }

#pragma unroll
    for (int j = 0; j < 4; ++j) psum[rg][4 * cg + j] = csum[j];
    __syncthreads();

    if (tid < 128) {
        float s = 0.f;
#pragma unroll
        for (int ww = 0; ww < 8; ++ww) s += psum[ww][tid];
        g_partial[(h * 4 + mt) * DKD + tid] = s;
    }
}

// ---------------------------------------------------------------------------
// k_out: out[i, c, d] = v[h,i,k]*colsum[h,k] + f_a[i,d]   (c = h*128+k)
// colsum computed inline from 4 partials (uniform per-warp loads).
// 16.7M float4 streaming stores; HBM-write-bound.
// ---------------------------------------------------------------------------
__global__ void k_out(const float* __restrict__ f_a, float4* __restrict__ out) {
    int idx = blockIdx.x * 512 + threadIdx.x;   // 0..2^24-1
    int d4 = idx & 63;
    int c  = (idx >> 6) & 2047;
    int i  = idx >> 17;
    int h  = c >> 7;
    int k  = c & 127;

    float cs = g_partial[(h * 4 + 0) * DKD + k]
             + g_partial[(h * 4 + 1) * DKD + k]
             + g_partial[(h * 4 + 2) * DKD + k]
             + g_partial[(h * 4 + 3) * DKD + k];
    float s = g_qkv[((long)(2 * H + h) * NBOX + i) * DKD + k] * cs;
    float4 f = ((const float4*)f_a)[i * 64 + d4];
    __stcs(&out[idx], make_float4(s + f.x, s + f.y, s + f.z, s + f.w));
}

// ---------------------------------------------------------------------------
extern "C" void kernel_launch(void* const* d_in, const int* in_sizes, int n_in,
                              void* d_out, int out_size) {
    const float* f_a = (const float*)d_in[0];
    const float* pos = (const float*)d_in[1];
    const float* WG  = (const float*)d_in[2];
    const float* bg  = (const float*)d_in[3];
    const float* WK  = (const float*)d_in[4];
    const float* bk  = (const float*)d_in[5];
    const float* WQ  = (const float*)d_in[6];
    const float* bq  = (const float*)d_in[7];
    const float* WV  = (const float*)d_in[8];
    const float* bv  = (const float*)d_in[9];

    k_front<<<448, 256>>>(f_a, pos, WG, bg, WK, bk, WQ, bq, WV, bv);
    k_attn<<<dim3(4, 16), 256>>>();
    k_out<<<32768, 512>>>(f_a, (float4*)d_out);
}